// round 13
// baseline (speedup 1.0000x reference)
#include <cuda_runtime.h>

// URPE: out[b,h,i,j] = probs[b,h,i,j] * toe[h,i,j]
// toe[h,i,j] = (j>=i) ? w[h, 2048 + (j-i)] : w[h, i-j]
// B=2, H=16, L=2048, weights (16, 4096) f32.
//
// Persistent-CTA variant: 592 resident blocks (148 SM x 4) of 512 threads
// grid-stride over the 32768 (h,i) row-pairs; each iteration serves BOTH
// batch entries from one smem Toeplitz fill. Eliminates ~55 waves of CTA
// launch/retire turnover; L1 stays warm within the launch. Measured
// context: five structural variants plateau at 150.7-152.0us device,
// 84.8-85.4% DRAM (~6.75 TB/s) = the sm_103a mixed 1:1 R/W HBM3e ceiling.
// Streaming cache hints were 10us slower; MLP_p1=8 was 34us slower.

#define L_DIM 2048
#define N_ROWPAIRS 32768u
#define B_STRIDE_F4 (16ull * 2048ull * 512ull)   // one batch in float4 units

__global__ __launch_bounds__(512, 4)
void urpe_kernel(const float4* __restrict__ probs,
                 const float* __restrict__ w,
                 float4* __restrict__ out)
{
    __shared__ float toe_row[L_DIM];

    const int tid = threadIdx.x;                  // [0,512): one float4 column
    const unsigned int stride = gridDim.x;

    for (unsigned int blk = blockIdx.x; blk < N_ROWPAIRS; blk += stride) {
        const int i = (int)(blk & 2047u);
        const int h = (int)(blk >> 11);
        const float* __restrict__ wh = w + h * (2 * L_DIM);

        const unsigned long long base = (unsigned long long)blk * 512ull;
        const unsigned long long o0 = base + tid;
        const unsigned long long o1 = base + B_STRIDE_F4 + tid;

        // Front-batch both DRAM loads (independent of the smem fill).
        float4 v0 = probs[o0];
        float4 v1 = probs[o1];

        // Gather the Toeplitz row from L1/L2 into smem (coalesced).
        #pragma unroll
        for (int j = tid; j < L_DIM; j += 512) {
            int d = j - i;
            toe_row[j] = __ldg(&wh[d >= 0 ? 2048 + d : -d]);
        }
        __syncthreads();

        const float4 t = ((const float4*)toe_row)[tid];

        float4 r0, r1;
        r0.x = v0.x * t.x;  r0.y = v0.y * t.y;
        r0.z = v0.z * t.z;  r0.w = v0.w * t.w;
        r1.x = v1.x * t.x;  r1.y = v1.y * t.y;
        r1.z = v1.z * t.z;  r1.w = v1.w * t.w;

        out[o0] = r0;
        out[o1] = r1;

        // Protect smem from next iteration's refill while stores drain
        // register state (stores don't read smem; only the refill conflicts
        // with this iteration's toe4 reads, which are already consumed).
        __syncthreads();
    }
}

extern "C" void kernel_launch(void* const* d_in, const int* in_sizes, int n_in,
                              void* d_out, int out_size)
{
    const float4* probs = (const float4*)d_in[0];   // (2,16,2048,2048) f32
    const float*  w     = (const float*)d_in[1];    // (16, 4096) f32
    float4* out = (float4*)d_out;

    // Persistent grid: 148 SMs x 4 blocks/SM
    urpe_kernel<<<592, 512>>>(probs, w, out);
}

// round 14
// speedup vs baseline: 1.1126x; 1.1126x over previous
#include <cuda_runtime.h>

// URPE: out[b,h,i,j] = probs[b,h,i,j] * toe[h,i,j]
// toe[h,i,j] = (j>=i) ? w[h, 2048 + (j-i)] : w[h, i-j]
// B=2, H=16, L=2048, weights (16, 4096) f32.
//
// FINAL: one 256-thread block per (h,i) pair, serving BOTH batch entries
// (toe row is b-independent -> one coalesced smem fill per 32 KB of DRAM
// traffic). Best of 9 measured variants: 150.75us device, 85.4% DRAM
// (~6.77 TB/s) = the sm_103a mixed 1:1 R/W HBM3e ceiling; traffic (1.07 GB)
// is the information-theoretic minimum for this op.
// Measured dead-ends: streaming hints (__ldcs/__stcs) -10%% (evict-first
// defeats L2 writeback coalescing); MLP_p1=8 front-batch -22%% (L1tex-queue
// spread + occupancy); persistent CTAs -6%% (loop barriers serialize the
// DRAM stream that CLC block turnover overlaps for free).

#define L_DIM 2048
#define B_STRIDE_F4 (16ull * 2048ull * 512ull)   // one batch in float4 units

__global__ __launch_bounds__(256, 8)
void urpe_kernel(const float4* __restrict__ probs,
                 const float* __restrict__ w,
                 float4* __restrict__ out)
{
    __shared__ float toe_row[L_DIM];

    const unsigned int blk = blockIdx.x;          // h*2048 + i, 32768 blocks
    const int i = (int)(blk & 2047u);
    const int h = (int)(blk >> 11);
    const float* __restrict__ wh = w + h * (2 * L_DIM);

    const int tid = threadIdx.x;

    // Gather the Toeplitz row from L1/L2 into smem (coalesced, contiguous:
    // ascending addresses for j>=i, descending-contiguous for j<i).
    #pragma unroll
    for (int j = tid; j < L_DIM; j += 256) {
        int d = j - i;
        toe_row[j] = __ldg(&wh[d >= 0 ? 2048 + d : -d]);
    }
    __syncthreads();

    const float4* __restrict__ toe4 = (const float4*)toe_row;
    const float4 t0 = toe4[tid];
    const float4 t1 = toe4[tid + 256];

    const unsigned long long base = (unsigned long long)blk * 512ull;

    // Both batch entries share this toe row.
    #pragma unroll
    for (int b = 0; b < 2; ++b) {
        const unsigned long long o = base + b * B_STRIDE_F4;
        float4 v0 = probs[o + tid];
        float4 v1 = probs[o + tid + 256];
        float4 r0, r1;
        r0.x = v0.x * t0.x;  r0.y = v0.y * t0.y;
        r0.z = v0.z * t0.z;  r0.w = v0.w * t0.w;
        r1.x = v1.x * t1.x;  r1.y = v1.y * t1.y;
        r1.z = v1.z * t1.z;  r1.w = v1.w * t1.w;
        out[o + tid]       = r0;
        out[o + tid + 256] = r1;
    }
}

extern "C" void kernel_launch(void* const* d_in, const int* in_sizes, int n_in,
                              void* d_out, int out_size)
{
    const float4* probs = (const float4*)d_in[0];   // (2,16,2048,2048) f32
    const float*  w     = (const float*)d_in[1];    // (16, 4096) f32
    float4* out = (float4*)d_out;

    // 16*2048 = 32768 (h,i) blocks; each handles b=0 and b=1
    urpe_kernel<<<32768, 256>>>(probs, w, out);
}